// round 10
// baseline (speedup 1.0000x reference)
#include <cuda_runtime.h>
#include <cuda_fp16.h>
#include <math.h>

#define B_   1024
#define L_   32
#define K_   8
#define G_   8
#define C_   128
#define S_   32
#define GRID_MAIN 148
#define NTILES 32              // tiles of 256 rows (32 batch elems)
#define NITEMS (L_ * NTILES)   // 1024

__device__ unsigned char g_ci[B_ * L_];
__device__ unsigned int g_mask[B_ * G_ * L_];

// ---------- helpers ----------
__device__ __forceinline__ unsigned pack2h(float lo, float hi) {
    unsigned r;
    asm("cvt.rn.f16x2.f32 %0, %1, %2;" : "=r"(r) : "f"(hi), "f"(lo));
    return r;
}
__device__ __forceinline__ float2 unpack2h(unsigned u) {
    __half2 h = *reinterpret_cast<__half2*>(&u);
    return __half22float2(h);
}
__device__ __forceinline__ float silu_f(float x) {
    float h = 0.5f * x, t;
    asm("tanh.approx.f32 %0, %1;" : "=f"(t) : "f"(h));
    return fmaf(h, t, h);
}
__device__ __forceinline__ void mma_f16(float* c,
    unsigned a0, unsigned a1, unsigned a2, unsigned a3, unsigned b0, unsigned b1) {
    asm("mma.sync.aligned.m16n8k16.row.col.f32.f16.f16.f32 "
        "{%0,%1,%2,%3},{%4,%5,%6,%7},{%8,%9},{%0,%1,%2,%3};"
        : "+f"(c[0]), "+f"(c[1]), "+f"(c[2]), "+f"(c[3])
        : "r"(a0), "r"(a1), "r"(a2), "r"(a3), "r"(b0), "r"(b1));
}
// d=104 is the folded-bias constant-1 input column
__device__ __forceinline__ float xval(int d, unsigned Mw, bool tfl, int tgt,
                                      const float* zr, const float* zh) {
    if (d < 32)  return ((Mw >> d) & 1u) ? zr[d] : 0.0f;
    if (d < 64)  return (float)((Mw >> (d - 32)) & 1u);
    if (d < 72)  return (tfl && (d - 64) == tgt) ? 1.0f : 0.0f;
    if (d < 104) return zh[d - 72];
    return (d == 104) ? 1.0f : 0.0f;
}

// ---------- merged prep ----------
__global__ void prep_kernel(const float* __restrict__ tp, const float* __restrict__ ug,
                            const float* __restrict__ th, const float* __restrict__ ga,
                            const float* __restrict__ u_adj, float* __restrict__ out) {
    __shared__ unsigned char sc[L_];
    __shared__ float sep[K_ * K_];
    int b = blockIdx.x, t = threadIdx.x;
    if (t < L_) {
        const float* u = ug + (b * L_ + t) * K_;
        float best = -1e30f; int bi = 0;
#pragma unroll
        for (int k = 0; k < K_; k++) {
            float gum = -logf(-logf(u[k] + 1e-10f) + 1e-10f);
            float v = tp[t * K_ + k] + gum;
            if (v > best) { best = v; bi = k; }
        }
        sc[t] = (unsigned char)bi;
        g_ci[b * L_ + t] = (unsigned char)bi;
    } else if (t >= 64 && t < 128) {
        int e = t - 64;
        float s1 = 1.0f / (1.0f + expf(-th[e]));
        float s2 = 1.0f / (1.0f + expf(-ga[e]));
        sep[e] = s1 * s2;
    }
    if (t == 0) out[b] = 0.0f;
    __syncthreads();
    int g = t >> 5, l = t & 31;
    int cl = sc[l];
    unsigned bits = 0;
#pragma unroll
    for (int cj = 0; cj < K_; cj++) {
        float u = u_adj[((b * G_ + g) * K_ + cj) * K_ + cl];
        bits |= (u < sep[cj * K_ + cl]) ? (1u << cj) : 0u;
    }
    unsigned wv = 0;
#pragma unroll
    for (int j = 0; j < L_; j++) {
        unsigned mj = (bits >> sc[j]) & 1u;
        if (j == l) mj = 0;
        wv |= mj << j;
    }
    g_mask[(b * G_ + g) * L_ + l] = wv;
}

// ---------- smem layout (bytes) ----------
#define OFF_W1   0
#define OFF_W2   40960
#define OFF_SZS  81920
#define OFF_SZSH 86016
#define OFF_WB1  90112
#define OFF_B2   91136
#define OFF_P2   91648
#define SMEM_BYTES 93696

__global__ __launch_bounds__(256, 1) void main_kernel(
    const float* __restrict__ z_sample, const int* __restrict__ target,
    const float* __restrict__ z_mean,   const float* __restrict__ z_logstd,
    const float* __restrict__ z_shared,
    const float* __restrict__ W1, const float* __restrict__ b1g,
    const float* __restrict__ g1wg, const float* __restrict__ g1bg,
    const float* __restrict__ W2, const float* __restrict__ b2g,
    const float* __restrict__ g2wg, const float* __restrict__ g2bg,
    const float* __restrict__ W3g, const float* __restrict__ b3g,
    const float* __restrict__ tsc, float* __restrict__ out)
{
    extern __shared__ char smem[];
    uint2*  W1u2 = (uint2*)(smem + OFF_W1);
    uint2*  W2u2 = (uint2*)(smem + OFF_W2);
    const uint4* W1q4 = (const uint4*)(smem + OFF_W1);
    const uint4* W2q4 = (const uint4*)(smem + OFF_W2);
    float*  szs  = (float*)(smem + OFF_SZS);
    float*  szsh = (float*)(smem + OFF_SZSH);
    float4* sWB1 = (float4*)(smem + OFF_WB1);   // (g1w,g1b,g1w,g1b) per channel pair
    float2* sB2  = (float2*)(smem + OFF_B2);    // b2 channel pairs
    float4* sP2  = (float4*)(smem + OFF_P2);    // (g2w,g2b,w3_0,w3_1) per channel

    const int tid = threadIdx.x;
    const int wid = tid >> 5;
    const int lane = tid & 31;
    const int gid = lane >> 2;
    const int t4 = lane & 3;

    const int start = (int)(((long long)blockIdx.x * NITEMS) / GRID_MAIN);
    const int end   = (int)(((long long)(blockIdx.x + 1) * NITEMS) / GRID_MAIN);

    int cur_l = -1;
    float b3_0 = 0.f, b3_1 = 0.f, sc0 = 1.f, sc1 = 1.f, isc0 = 1.f, isc1 = 1.f;

    for (int item = start; item < end; item++) {
        const int l = item >> 5;
        const int tile = item & 31;

        if (l != cur_l) {
            __syncthreads();
            const float* W1g = W1 + l * C_ * 104;
            for (int idx = tid; idx < 128 * 32; idx += 256) {
                int c = idx >> 5, s = idx & 31;
                int kk = s >> 2, tq = s & 3;
                int d0 = kk * 16 + tq * 2, d1 = d0 + 8;
                // fold b1 into the d=104 constant-1 column
                float w00 = (d0 < 104) ? W1g[c * 104 + d0]
                                       : ((d0 == 104) ? b1g[l * C_ + c] : 0.0f);
                float w01 = (d0 + 1 < 104) ? W1g[c * 104 + d0 + 1] : 0.0f;
                float w10 = (d1 < 104) ? W1g[c * 104 + d1]
                                       : ((d1 == 104) ? b1g[l * C_ + c] : 0.0f);
                float w11 = (d1 + 1 < 104) ? W1g[c * 104 + d1 + 1] : 0.0f;
                W1u2[c * 40 + (kk >> 1) * 8 + tq * 2 + (kk & 1)] =
                    make_uint2(pack2h(w00, w01), pack2h(w10, w11));
            }
            const float* W2g = W2 + l * C_ * C_;
            for (int idx = tid; idx < 128 * 32; idx += 256) {
                int c = idx >> 5, s = idx & 31;
                int kk = s >> 2, tq = s & 3;
                int d0 = kk * 16 + tq * 2, d1 = d0 + 8;
                W2u2[c * 40 + (kk >> 1) * 8 + tq * 2 + (kk & 1)] =
                    make_uint2(pack2h(W2g[c * C_ + d0], W2g[c * C_ + d0 + 1]),
                               pack2h(W2g[c * C_ + d1], W2g[c * C_ + d1 + 1]));
            }
            if (tid < 64) {
                int c0 = 2 * tid;
                sWB1[tid] = make_float4(g1wg[l * C_ + c0], g1bg[l * C_ + c0],
                                        g1wg[l * C_ + c0 + 1], g1bg[l * C_ + c0 + 1]);
                sB2[tid]  = make_float2(b2g[l * C_ + c0], b2g[l * C_ + c0 + 1]);
            }
            if (tid < 128) {
                sP2[tid] = make_float4(g2wg[l * C_ + tid], g2bg[l * C_ + tid],
                                       W3g[l * 2 * C_ + tid], W3g[l * 2 * C_ + C_ + tid]);
            }
            b3_0 = b3g[l * 2]; b3_1 = b3g[l * 2 + 1];
            sc0 = __expf(tsc[l * 2]); sc1 = __expf(tsc[l * 2 + 1]);
            isc0 = 1.0f / sc0; isc1 = 1.0f / sc1;
            __syncthreads();
            cur_l = l;
        }

        // stage z rows for this tile (32 b's)
        __syncthreads();
        for (int idx = tid; idx < 1024; idx += 256) {
            szs[idx]  = z_sample[tile * 32 * L_ + idx];
            szsh[idx] = z_shared[tile * 32 * S_ + idx];
        }
        __syncthreads();

        // warp owns 32 rows: 4 chunks of 8; thread rows = gid + {0,8,16,24}
        unsigned Mw[4];
        bool tf[4];
        int tg[4];
#pragma unroll
        for (int k = 0; k < 4; k++) {
            int grow = tile * 256 + wid * 32 + k * 8 + gid;
            int bb = tile * 32 + wid * 4 + k;
            Mw[k] = g_mask[grow * L_ + l];
            tg[k] = target[bb];
            tf[k] = (g_ci[bb * L_ + l] == tg[k]);
        }

        // ---- bufA: A1 fragments during MMA1 (56 slots), MMA2 outputs after (64 slots)
        unsigned bufA[64];
        {
            const float* zr0 = szs  + (wid * 4 + 0) * 32;
            const float* zr1 = szs  + (wid * 4 + 1) * 32;
            const float* zr2 = szs  + (wid * 4 + 2) * 32;
            const float* zr3 = szs  + (wid * 4 + 3) * 32;
            const float* zh0 = szsh + (wid * 4 + 0) * 32;
            const float* zh1 = szsh + (wid * 4 + 1) * 32;
            const float* zh2 = szsh + (wid * 4 + 2) * 32;
            const float* zh3 = szsh + (wid * 4 + 3) * 32;
#pragma unroll
            for (int kk = 0; kk < 7; kk++) {
                int db = kk * 16 + t4 * 2;
                bufA[kk * 8 + 0] = pack2h(xval(db,     Mw[0], tf[0], tg[0], zr0, zh0),
                                          xval(db + 1, Mw[0], tf[0], tg[0], zr0, zh0));
                bufA[kk * 8 + 1] = pack2h(xval(db,     Mw[1], tf[1], tg[1], zr1, zh1),
                                          xval(db + 1, Mw[1], tf[1], tg[1], zr1, zh1));
                bufA[kk * 8 + 2] = pack2h(xval(db + 8, Mw[0], tf[0], tg[0], zr0, zh0),
                                          xval(db + 9, Mw[0], tf[0], tg[0], zr0, zh0));
                bufA[kk * 8 + 3] = pack2h(xval(db + 8, Mw[1], tf[1], tg[1], zr1, zh1),
                                          xval(db + 9, Mw[1], tf[1], tg[1], zr1, zh1));
                bufA[kk * 8 + 4] = pack2h(xval(db,     Mw[2], tf[2], tg[2], zr2, zh2),
                                          xval(db + 1, Mw[2], tf[2], tg[2], zr2, zh2));
                bufA[kk * 8 + 5] = pack2h(xval(db,     Mw[3], tf[3], tg[3], zr3, zh3),
                                          xval(db + 1, Mw[3], tf[3], tg[3], zr3, zh3));
                bufA[kk * 8 + 6] = pack2h(xval(db + 8, Mw[2], tf[2], tg[2], zr2, zh2),
                                          xval(db + 9, Mw[2], tf[2], tg[2], zr2, zh2));
                bufA[kk * 8 + 7] = pack2h(xval(db + 8, Mw[3], tf[3], tg[3], zr3, zh3),
                                          xval(db + 9, Mw[3], tf[3], tg[3], zr3, zh3));
            }
        }

        // ---- MMA1 (nt-outer; bias folded into W1) ----
        unsigned vh0[16][2], vh1[16][2];
        float s[4] = {0.f, 0.f, 0.f, 0.f}, q[4] = {0.f, 0.f, 0.f, 0.f};
#pragma unroll
        for (int nt = 0; nt < 16; nt++) {
            float a0[4] = {0.f, 0.f, 0.f, 0.f}, a1[4] = {0.f, 0.f, 0.f, 0.f};
            const uint4* bp = W1q4 + (nt * 8 + gid) * 20 + t4;
#pragma unroll
            for (int j = 0; j < 4; j++) {
                uint4 bqv = bp[j * 4];
                mma_f16(a0, bufA[16*j+0], bufA[16*j+1], bufA[16*j+2], bufA[16*j+3], bqv.x, bqv.y);
                mma_f16(a1, bufA[16*j+4], bufA[16*j+5], bufA[16*j+6], bufA[16*j+7], bqv.x, bqv.y);
                if (j < 3) {
                    mma_f16(a0, bufA[16*j+8],  bufA[16*j+9],  bufA[16*j+10], bufA[16*j+11], bqv.z, bqv.w);
                    mma_f16(a1, bufA[16*j+12], bufA[16*j+13], bufA[16*j+14], bufA[16*j+15], bqv.z, bqv.w);
                }
            }
            s[0] += a0[0] + a0[1]; q[0] += a0[0]*a0[0] + a0[1]*a0[1];
            s[1] += a0[2] + a0[3]; q[1] += a0[2]*a0[2] + a0[3]*a0[3];
            s[2] += a1[0] + a1[1]; q[2] += a1[0]*a1[0] + a1[1]*a1[1];
            s[3] += a1[2] + a1[3]; q[3] += a1[2]*a1[2] + a1[3]*a1[3];
            vh0[nt][0] = pack2h(a0[0], a0[1]); vh0[nt][1] = pack2h(a0[2], a0[3]);
            vh1[nt][0] = pack2h(a1[0], a1[1]); vh1[nt][1] = pack2h(a1[2], a1[3]);
        }
#pragma unroll
        for (int o = 1; o <= 2; o <<= 1)
#pragma unroll
            for (int k = 0; k < 4; k++) {
                s[k] += __shfl_xor_sync(0xffffffffu, s[k], o);
                q[k] += __shfl_xor_sync(0xffffffffu, q[k], o);
            }
        float mu[4], inv[4];
#pragma unroll
        for (int k = 0; k < 4; k++) {
            mu[k] = s[k] * (1.0f / 128.0f);
            inv[k] = rsqrtf(q[k] * (1.0f / 128.0f) - mu[k] * mu[k] + 1e-5f);
        }

        // ---- GN1 + SiLU in place (vh becomes A2 fragments) ----
#pragma unroll
        for (int nt = 0; nt < 16; nt++) {
            float4 wb = sWB1[nt * 4 + t4];
            float2 f;
            f = unpack2h(vh0[nt][0]);
            vh0[nt][0] = pack2h(silu_f((f.x - mu[0]) * inv[0] * wb.x + wb.y),
                                silu_f((f.y - mu[0]) * inv[0] * wb.z + wb.w));
            f = unpack2h(vh0[nt][1]);
            vh0[nt][1] = pack2h(silu_f((f.x - mu[1]) * inv[1] * wb.x + wb.y),
                                silu_f((f.y - mu[1]) * inv[1] * wb.z + wb.w));
            f = unpack2h(vh1[nt][0]);
            vh1[nt][0] = pack2h(silu_f((f.x - mu[2]) * inv[2] * wb.x + wb.y),
                                silu_f((f.y - mu[2]) * inv[2] * wb.z + wb.w));
            f = unpack2h(vh1[nt][1]);
            vh1[nt][1] = pack2h(silu_f((f.x - mu[3]) * inv[3] * wb.x + wb.y),
                                silu_f((f.y - mu[3]) * inv[3] * wb.z + wb.w));
        }

        // ---- MMA2 (A2 = vh; outputs overwrite bufA) ----
#pragma unroll
        for (int k = 0; k < 4; k++) { s[k] = 0.f; q[k] = 0.f; }
#pragma unroll
        for (int nt = 0; nt < 16; nt++) {
            float a0[4] = {0.f, 0.f, 0.f, 0.f}, a1[4] = {0.f, 0.f, 0.f, 0.f};
            const uint4* bp = W2q4 + (nt * 8 + gid) * 20 + t4;
#pragma unroll
            for (int j = 0; j < 4; j++) {
                uint4 bqv = bp[j * 4];
                mma_f16(a0, vh0[4*j][0],   vh0[4*j][1],   vh0[4*j+1][0], vh0[4*j+1][1], bqv.x, bqv.y);
                mma_f16(a1, vh1[4*j][0],   vh1[4*j][1],   vh1[4*j+1][0], vh1[4*j+1][1], bqv.x, bqv.y);
                mma_f16(a0, vh0[4*j+2][0], vh0[4*j+2][1], vh0[4*j+3][0], vh0[4*j+3][1], bqv.z, bqv.w);
                mma_f16(a1, vh1[4*j+2][0], vh1[4*j+2][1], vh1[4*j+3][0], vh1[4*j+3][1], bqv.z, bqv.w);
            }
            float2 bb = sB2[nt * 4 + t4];
            a0[0] += bb.x; a0[1] += bb.y; a0[2] += bb.x; a0[3] += bb.y;
            a1[0] += bb.x; a1[1] += bb.y; a1[2] += bb.x; a1[3] += bb.y;
            s[0] += a0[0] + a0[1]; q[0] += a0[0]*a0[0] + a0[1]*a0[1];
            s[1] += a0[2] + a0[3]; q[1] += a0[2]*a0[2] + a0[3]*a0[3];
            s[2] += a1[0] + a1[1]; q[2] += a1[0]*a1[0] + a1[1]*a1[1];
            s[3] += a1[2] + a1[3]; q[3] += a1[2]*a1[2] + a1[3]*a1[3];
            bufA[nt * 4 + 0] = pack2h(a0[0], a0[1]);
            bufA[nt * 4 + 1] = pack2h(a0[2], a0[3]);
            bufA[nt * 4 + 2] = pack2h(a1[0], a1[1]);
            bufA[nt * 4 + 3] = pack2h(a1[2], a1[3]);
        }
#pragma unroll
        for (int o = 1; o <= 2; o <<= 1)
#pragma unroll
            for (int k = 0; k < 4; k++) {
                s[k] += __shfl_xor_sync(0xffffffffu, s[k], o);
                q[k] += __shfl_xor_sync(0xffffffffu, q[k], o);
            }
#pragma unroll
        for (int k = 0; k < 4; k++) {
            mu[k] = s[k] * (1.0f / 128.0f);
            inv[k] = rsqrtf(q[k] * (1.0f / 128.0f) - mu[k] * mu[k] + 1e-5f);
        }

        // ---- GN2 + SiLU + layer3 + KL ----
        float p0[4] = {0.f, 0.f, 0.f, 0.f}, p1[4] = {0.f, 0.f, 0.f, 0.f};
#pragma unroll
        for (int nt = 0; nt < 16; nt++) {
            float4 pa = sP2[nt * 8 + 2 * t4];       // channel c
            float4 pb = sP2[nt * 8 + 2 * t4 + 1];   // channel c+1
            float2 f;
            f = unpack2h(bufA[nt * 4 + 0]);
            {
                float h0 = silu_f((f.x - mu[0]) * inv[0] * pa.x + pa.y);
                float h1 = silu_f((f.y - mu[0]) * inv[0] * pb.x + pb.y);
                p0[0] += h0 * pa.z + h1 * pb.z;  p1[0] += h0 * pa.w + h1 * pb.w;
            }
            f = unpack2h(bufA[nt * 4 + 1]);
            {
                float h0 = silu_f((f.x - mu[1]) * inv[1] * pa.x + pa.y);
                float h1 = silu_f((f.y - mu[1]) * inv[1] * pb.x + pb.y);
                p0[1] += h0 * pa.z + h1 * pb.z;  p1[1] += h0 * pa.w + h1 * pb.w;
            }
            f = unpack2h(bufA[nt * 4 + 2]);
            {
                float h0 = silu_f((f.x - mu[2]) * inv[2] * pa.x + pa.y);
                float h1 = silu_f((f.y - mu[2]) * inv[2] * pb.x + pb.y);
                p0[2] += h0 * pa.z + h1 * pb.z;  p1[2] += h0 * pa.w + h1 * pb.w;
            }
            f = unpack2h(bufA[nt * 4 + 3]);
            {
                float h0 = silu_f((f.x - mu[3]) * inv[3] * pa.x + pa.y);
                float h1 = silu_f((f.y - mu[3]) * inv[3] * pb.x + pb.y);
                p0[3] += h0 * pa.z + h1 * pb.z;  p1[3] += h0 * pa.w + h1 * pb.w;
            }
        }
#pragma unroll
        for (int o = 1; o <= 2; o <<= 1)
#pragma unroll
            for (int k = 0; k < 4; k++) {
                p0[k] += __shfl_xor_sync(0xffffffffu, p0[k], o);
                p1[k] += __shfl_xor_sync(0xffffffffu, p1[k], o);
            }
        if (t4 == 0) {
#pragma unroll
            for (int k = 0; k < 4; k++) {
                int bb = tile * 32 + wid * 4 + k;
                float o0 = p0[k] + b3_0, o1 = p1[k] + b3_1;
                float pm = tanhf(o0 * isc0) * sc0;
                float pl = tanhf(o1 * isc1) * sc1;
                float zl = z_logstd[bb * L_ + l], zmn = z_mean[bb * L_ + l];
                float dmu = zmn - pm;
                float kld = pl - zl + (__expf(2.0f * zl) + dmu * dmu) * 0.5f * __expf(-2.0f * pl) - 0.5f;
                atomicAdd(out + bb, kld * 0.125f);
            }
        }
    }
}

extern "C" void kernel_launch(void* const* d_in, const int* in_sizes, int n_in,
                              void* d_out, int out_size) {
    const float* z_sample      = (const float*)d_in[0];
    const int*   target        = (const int*)  d_in[1];
    const float* z_mean        = (const float*)d_in[2];
    const float* z_logstd      = (const float*)d_in[3];
    const float* z_shared      = (const float*)d_in[4];
    const float* u_gumbel      = (const float*)d_in[5];
    const float* u_adj         = (const float*)d_in[6];
    const float* target_params = (const float*)d_in[7];
    const float* enco_theta    = (const float*)d_in[8];
    const float* enco_gamma    = (const float*)d_in[9];
    const float* W1            = (const float*)d_in[10];
    const float* b1            = (const float*)d_in[11];
    const float* gn1_w         = (const float*)d_in[12];
    const float* gn1_b         = (const float*)d_in[13];
    const float* W2            = (const float*)d_in[14];
    const float* b2            = (const float*)d_in[15];
    const float* gn2_w         = (const float*)d_in[16];
    const float* gn2_b         = (const float*)d_in[17];
    const float* W3            = (const float*)d_in[18];
    const float* b3            = (const float*)d_in[19];
    const float* tanh_scale    = (const float*)d_in[20];
    float* out = (float*)d_out;

    prep_kernel<<<B_, 256>>>(target_params, u_gumbel, enco_theta, enco_gamma, u_adj, out);

    cudaFuncSetAttribute(main_kernel, cudaFuncAttributeMaxDynamicSharedMemorySize, SMEM_BYTES);
    main_kernel<<<GRID_MAIN, 256, SMEM_BYTES>>>(
        z_sample, target, z_mean, z_logstd, z_shared,
        W1, b1, gn1_w, gn1_b, W2, b2, gn2_w, gn2_b, W3, b3, tanh_scale, out);
}

// round 11
// speedup vs baseline: 1.1480x; 1.1480x over previous
#include <cuda_runtime.h>
#include <cuda_fp16.h>
#include <math.h>

#define B_   1024
#define L_   32
#define K_   8
#define G_   8
#define C_   128
#define S_   32
#define GRID_MAIN 296
#define NTILES 64
#define NITEMS (L_ * NTILES)

__device__ unsigned char g_ci[B_ * L_];
__device__ unsigned int g_mask[B_ * G_ * L_];

// ---------- helpers ----------
__device__ __forceinline__ unsigned pack2h(float lo, float hi) {
    unsigned r;
    asm("cvt.rn.f16x2.f32 %0, %1, %2;" : "=r"(r) : "f"(hi), "f"(lo));
    return r;
}
__device__ __forceinline__ float silu_f(float x) {
    float h = 0.5f * x, t;
    asm("tanh.approx.f32 %0, %1;" : "=f"(t) : "f"(h));
    return fmaf(h, t, h);
}
__device__ __forceinline__ void mma_f16(float* c,
    unsigned a0, unsigned a1, unsigned a2, unsigned a3, unsigned b0, unsigned b1) {
    asm("mma.sync.aligned.m16n8k16.row.col.f32.f16.f16.f32 "
        "{%0,%1,%2,%3},{%4,%5,%6,%7},{%8,%9},{%0,%1,%2,%3};"
        : "+f"(c[0]), "+f"(c[1]), "+f"(c[2]), "+f"(c[3])
        : "r"(a0), "r"(a1), "r"(a2), "r"(a3), "r"(b0), "r"(b1));
}
// d=104 is the folded-bias constant-1 input column
__device__ __forceinline__ float xval(int d, unsigned Mw, bool tfl, int tgt,
                                      const float* zr, const float* zh) {
    if (d < 32)  return ((Mw >> d) & 1u) ? zr[d] : 0.0f;
    if (d < 64)  return (float)((Mw >> (d - 32)) & 1u);
    if (d < 72)  return (tfl && (d - 64) == tgt) ? 1.0f : 0.0f;
    if (d < 104) return zh[d - 72];
    return (d == 104) ? 1.0f : 0.0f;
}

// ---------- merged prep ----------
__global__ void prep_kernel(const float* __restrict__ tp, const float* __restrict__ ug,
                            const float* __restrict__ th, const float* __restrict__ ga,
                            const float* __restrict__ u_adj, float* __restrict__ out) {
    __shared__ unsigned char sc[L_];
    __shared__ float sep[K_ * K_];
    int b = blockIdx.x, t = threadIdx.x;
    if (t < L_) {
        const float* u = ug + (b * L_ + t) * K_;
        float best = -1e30f; int bi = 0;
#pragma unroll
        for (int k = 0; k < K_; k++) {
            float gum = -logf(-logf(u[k] + 1e-10f) + 1e-10f);
            float v = tp[t * K_ + k] + gum;
            if (v > best) { best = v; bi = k; }
        }
        sc[t] = (unsigned char)bi;
        g_ci[b * L_ + t] = (unsigned char)bi;
    } else if (t >= 64 && t < 128) {
        int e = t - 64;
        float s1 = 1.0f / (1.0f + expf(-th[e]));
        float s2 = 1.0f / (1.0f + expf(-ga[e]));
        sep[e] = s1 * s2;
    }
    if (t == 0) out[b] = 0.0f;
    __syncthreads();
    int g = t >> 5, l = t & 31;
    int cl = sc[l];
    unsigned bits = 0;
#pragma unroll
    for (int cj = 0; cj < K_; cj++) {
        float u = u_adj[((b * G_ + g) * K_ + cj) * K_ + cl];
        bits |= (u < sep[cj * K_ + cl]) ? (1u << cj) : 0u;
    }
    unsigned wv = 0;
#pragma unroll
    for (int j = 0; j < L_; j++) {
        unsigned mj = (bits >> sc[j]) & 1u;
        if (j == l) mj = 0;
        wv |= mj << j;
    }
    g_mask[(b * G_ + g) * L_ + l] = wv;
}

// ---------- smem layout (bytes) ----------
// W1/W2: 128 rows x 320B (stride 320 == 64 mod 128 -> conflict-free LDS.128)
#define OFF_W1   0
#define OFF_W2   40960
#define OFF_SZS  81920
#define OFF_SZSH 83968
#define OFF_WB1  86016
#define OFF_B2   87040
#define OFF_P2   87552
#define SMEM_BYTES 89600

__global__ __launch_bounds__(256, 2) void main_kernel(
    const float* __restrict__ z_sample, const int* __restrict__ target,
    const float* __restrict__ z_mean,   const float* __restrict__ z_logstd,
    const float* __restrict__ z_shared,
    const float* __restrict__ W1, const float* __restrict__ b1g,
    const float* __restrict__ g1wg, const float* __restrict__ g1bg,
    const float* __restrict__ W2, const float* __restrict__ b2g,
    const float* __restrict__ g2wg, const float* __restrict__ g2bg,
    const float* __restrict__ W3g, const float* __restrict__ b3g,
    const float* __restrict__ tsc, float* __restrict__ out)
{
    extern __shared__ char smem[];
    uint2*  W1u2 = (uint2*)(smem + OFF_W1);
    uint2*  W2u2 = (uint2*)(smem + OFF_W2);
    const uint4* W1q4 = (const uint4*)(smem + OFF_W1);
    const uint4* W2q4 = (const uint4*)(smem + OFF_W2);
    float*  szs  = (float*)(smem + OFF_SZS);
    float*  szsh = (float*)(smem + OFF_SZSH);
    float4* sWB1 = (float4*)(smem + OFF_WB1);   // (g1w[c0],g1b[c0],g1w[c0+1],g1b[c0+1])
    float2* sB2  = (float2*)(smem + OFF_B2);    // b2 channel pairs
    float4* sP2  = (float4*)(smem + OFF_P2);    // (g2w,g2b,w3_0,w3_1) per channel

    const int tid = threadIdx.x;
    const int wid = tid >> 5;
    const int lane = tid & 31;
    const int gid = lane >> 2;
    const int t4 = lane & 3;

    const int start = (int)(((long long)blockIdx.x * NITEMS) / GRID_MAIN);
    const int end   = (int)(((long long)(blockIdx.x + 1) * NITEMS) / GRID_MAIN);

    int cur_l = -1;
    float b3_0 = 0.f, b3_1 = 0.f, sc0 = 1.f, sc1 = 1.f, isc0 = 1.f, isc1 = 1.f;

    for (int item = start; item < end; item++) {
        const int l = item >> 6;
        const int tile = item & 63;

        if (l != cur_l) {
            __syncthreads();
            const float* W1g = W1 + l * C_ * 104;
            for (int idx = tid; idx < 128 * 32; idx += 256) {
                int c = idx >> 5, s = idx & 31;
                int kk = s >> 2, tq = s & 3;
                int d0 = kk * 16 + tq * 2, d1 = d0 + 8;
                // fold b1 into the d=104 constant-1 column
                float w00 = (d0 < 104) ? W1g[c * 104 + d0]
                                       : ((d0 == 104) ? b1g[l * C_ + c] : 0.0f);
                float w01 = (d0 + 1 < 104) ? W1g[c * 104 + d0 + 1] : 0.0f;
                float w10 = (d1 < 104) ? W1g[c * 104 + d1]
                                       : ((d1 == 104) ? b1g[l * C_ + c] : 0.0f);
                float w11 = (d1 + 1 < 104) ? W1g[c * 104 + d1 + 1] : 0.0f;
                W1u2[c * 40 + (kk >> 1) * 8 + tq * 2 + (kk & 1)] =
                    make_uint2(pack2h(w00, w01), pack2h(w10, w11));
            }
            const float* W2g = W2 + l * C_ * C_;
            for (int idx = tid; idx < 128 * 32; idx += 256) {
                int c = idx >> 5, s = idx & 31;
                int kk = s >> 2, tq = s & 3;
                int d0 = kk * 16 + tq * 2, d1 = d0 + 8;
                W2u2[c * 40 + (kk >> 1) * 8 + tq * 2 + (kk & 1)] =
                    make_uint2(pack2h(W2g[c * C_ + d0], W2g[c * C_ + d0 + 1]),
                               pack2h(W2g[c * C_ + d1], W2g[c * C_ + d1 + 1]));
            }
            if (tid < 64) {
                int c0 = 2 * tid;
                sWB1[tid] = make_float4(g1wg[l * C_ + c0], g1bg[l * C_ + c0],
                                        g1wg[l * C_ + c0 + 1], g1bg[l * C_ + c0 + 1]);
                sB2[tid]  = make_float2(b2g[l * C_ + c0], b2g[l * C_ + c0 + 1]);
            }
            if (tid < 128) {
                sP2[tid] = make_float4(g2wg[l * C_ + tid], g2bg[l * C_ + tid],
                                       W3g[l * 2 * C_ + tid], W3g[l * 2 * C_ + C_ + tid]);
            }
            b3_0 = b3g[l * 2]; b3_1 = b3g[l * 2 + 1];
            sc0 = __expf(tsc[l * 2]); sc1 = __expf(tsc[l * 2 + 1]);
            isc0 = 1.0f / sc0; isc1 = 1.0f / sc1;
            __syncthreads();
            cur_l = l;
        }

        // stage z rows for this tile (16 b's)
        __syncthreads();
        for (int idx = tid; idx < 512; idx += 256) {
            szs[idx]  = z_sample[tile * 16 * L_ + idx];
            szsh[idx] = z_shared[tile * 16 * S_ + idx];
        }
        __syncthreads();

        // per-thread rows: r0 = wid*16+gid, r1 = r0+8
        const int grow0 = tile * 128 + wid * 16 + gid;
        const int grow1 = grow0 + 8;
        const int b0i = grow0 >> 3, b1i = grow1 >> 3;
        const unsigned Mw0 = g_mask[grow0 * L_ + l];
        const unsigned Mw1 = g_mask[grow1 * L_ + l];
        const int tgt0 = target[b0i], tgt1 = target[b1i];
        const bool tf0 = (g_ci[b0i * L_ + l] == tgt0);
        const bool tf1 = (g_ci[b1i * L_ + l] == tgt1);
        const float* zr0 = szs  + (2 * wid) * 32;
        const float* zr1 = zr0 + 32;
        const float* zh0 = szsh + (2 * wid) * 32;
        const float* zh1 = zh0 + 32;

        // ---- build A1 fragments (fp16); kk=6 second half carries the bias column ----
        unsigned Ah[7][4];
#pragma unroll
        for (int kk = 0; kk < 7; kk++) {
            int db = kk * 16 + t4 * 2;
            Ah[kk][0] = pack2h(xval(db,     Mw0, tf0, tgt0, zr0, zh0),
                               xval(db + 1, Mw0, tf0, tgt0, zr0, zh0));
            Ah[kk][1] = pack2h(xval(db,     Mw1, tf1, tgt1, zr1, zh1),
                               xval(db + 1, Mw1, tf1, tgt1, zr1, zh1));
            Ah[kk][2] = pack2h(xval(db + 8, Mw0, tf0, tgt0, zr0, zh0),
                               xval(db + 9, Mw0, tf0, tgt0, zr0, zh0));
            Ah[kk][3] = pack2h(xval(db + 8, Mw1, tf1, tgt1, zr1, zh1),
                               xval(db + 9, Mw1, tf1, tgt1, zr1, zh1));
        }

        // ---- MMA1 (bias folded into W1) ----
        float acc[16][4];
#pragma unroll
        for (int nt = 0; nt < 16; nt++)
#pragma unroll
            for (int i = 0; i < 4; i++) acc[nt][i] = 0.0f;

#pragma unroll
        for (int nt = 0; nt < 16; nt++) {
            const uint4* bp = W1q4 + (nt * 8 + gid) * 20 + t4;
#pragma unroll
            for (int j = 0; j < 4; j++) {
                uint4 bq = bp[j * 4];
                mma_f16(acc[nt], Ah[2*j][0], Ah[2*j][1], Ah[2*j][2], Ah[2*j][3], bq.x, bq.y);
                if (j < 3)
                    mma_f16(acc[nt], Ah[2*j+1][0], Ah[2*j+1][1], Ah[2*j+1][2], Ah[2*j+1][3], bq.z, bq.w);
            }
        }

        // ---- GN1 + SiLU -> A2 fragments ----
        float s0 = 0.f, q0 = 0.f, s1 = 0.f, q1 = 0.f;
#pragma unroll
        for (int nt = 0; nt < 16; nt++) {
            s0 += acc[nt][0] + acc[nt][1];
            q0 += acc[nt][0] * acc[nt][0] + acc[nt][1] * acc[nt][1];
            s1 += acc[nt][2] + acc[nt][3];
            q1 += acc[nt][2] * acc[nt][2] + acc[nt][3] * acc[nt][3];
        }
#pragma unroll
        for (int o = 1; o <= 2; o <<= 1) {
            s0 += __shfl_xor_sync(0xffffffffu, s0, o);
            q0 += __shfl_xor_sync(0xffffffffu, q0, o);
            s1 += __shfl_xor_sync(0xffffffffu, s1, o);
            q1 += __shfl_xor_sync(0xffffffffu, q1, o);
        }
        float mu0 = s0 * (1.0f / 128.0f);
        float inv0 = rsqrtf(q0 * (1.0f / 128.0f) - mu0 * mu0 + 1e-5f);
        float mu1 = s1 * (1.0f / 128.0f);
        float inv1 = rsqrtf(q1 * (1.0f / 128.0f) - mu1 * mu1 + 1e-5f);

        unsigned A2h[8][4];
#pragma unroll
        for (int kk = 0; kk < 8; kk++) {
            int nt0 = 2 * kk, nt1 = 2 * kk + 1;
            float4 wb0 = sWB1[nt0 * 4 + t4];
            float4 wb1 = sWB1[nt1 * 4 + t4];
            float h00 = silu_f((acc[nt0][0] - mu0) * inv0 * wb0.x + wb0.y);
            float h01 = silu_f((acc[nt0][1] - mu0) * inv0 * wb0.z + wb0.w);
            float h02 = silu_f((acc[nt0][2] - mu1) * inv1 * wb0.x + wb0.y);
            float h03 = silu_f((acc[nt0][3] - mu1) * inv1 * wb0.z + wb0.w);
            float h10 = silu_f((acc[nt1][0] - mu0) * inv0 * wb1.x + wb1.y);
            float h11 = silu_f((acc[nt1][1] - mu0) * inv0 * wb1.z + wb1.w);
            float h12 = silu_f((acc[nt1][2] - mu1) * inv1 * wb1.x + wb1.y);
            float h13 = silu_f((acc[nt1][3] - mu1) * inv1 * wb1.z + wb1.w);
            A2h[kk][0] = pack2h(h00, h01);
            A2h[kk][1] = pack2h(h02, h03);
            A2h[kk][2] = pack2h(h10, h11);
            A2h[kk][3] = pack2h(h12, h13);
        }

        // ---- MMA2 ----
#pragma unroll
        for (int nt = 0; nt < 16; nt++)
#pragma unroll
            for (int i = 0; i < 4; i++) acc[nt][i] = 0.0f;

#pragma unroll
        for (int nt = 0; nt < 16; nt++) {
            const uint4* bp = W2q4 + (nt * 8 + gid) * 20 + t4;
#pragma unroll
            for (int j = 0; j < 4; j++) {
                uint4 bq = bp[j * 4];
                mma_f16(acc[nt], A2h[2*j][0], A2h[2*j][1], A2h[2*j][2], A2h[2*j][3], bq.x, bq.y);
                mma_f16(acc[nt], A2h[2*j+1][0], A2h[2*j+1][1], A2h[2*j+1][2], A2h[2*j+1][3], bq.z, bq.w);
            }
        }

        // ---- GN2 + SiLU + layer3 + KL ----
        s0 = 0.f; q0 = 0.f; s1 = 0.f; q1 = 0.f;
#pragma unroll
        for (int nt = 0; nt < 16; nt++) {
            float2 bb = sB2[nt * 4 + t4];
            acc[nt][0] += bb.x; acc[nt][1] += bb.y;
            acc[nt][2] += bb.x; acc[nt][3] += bb.y;
            s0 += acc[nt][0] + acc[nt][1];
            q0 += acc[nt][0] * acc[nt][0] + acc[nt][1] * acc[nt][1];
            s1 += acc[nt][2] + acc[nt][3];
            q1 += acc[nt][2] * acc[nt][2] + acc[nt][3] * acc[nt][3];
        }
#pragma unroll
        for (int o = 1; o <= 2; o <<= 1) {
            s0 += __shfl_xor_sync(0xffffffffu, s0, o);
            q0 += __shfl_xor_sync(0xffffffffu, q0, o);
            s1 += __shfl_xor_sync(0xffffffffu, s1, o);
            q1 += __shfl_xor_sync(0xffffffffu, q1, o);
        }
        mu0 = s0 * (1.0f / 128.0f);
        inv0 = rsqrtf(q0 * (1.0f / 128.0f) - mu0 * mu0 + 1e-5f);
        mu1 = s1 * (1.0f / 128.0f);
        inv1 = rsqrtf(q1 * (1.0f / 128.0f) - mu1 * mu1 + 1e-5f);

        float p00 = 0.f, p10 = 0.f, p01 = 0.f, p11 = 0.f;
#pragma unroll
        for (int nt = 0; nt < 16; nt++) {
            float4 pa = sP2[nt * 8 + 2 * t4];
            float4 pb = sP2[nt * 8 + 2 * t4 + 1];
            float h0 = silu_f((acc[nt][0] - mu0) * inv0 * pa.x + pa.y);
            float h1 = silu_f((acc[nt][1] - mu0) * inv0 * pb.x + pb.y);
            float h2 = silu_f((acc[nt][2] - mu1) * inv1 * pa.x + pa.y);
            float h3 = silu_f((acc[nt][3] - mu1) * inv1 * pb.x + pb.y);
            p00 += h0 * pa.z + h1 * pb.z;
            p10 += h0 * pa.w + h1 * pb.w;
            p01 += h2 * pa.z + h3 * pb.z;
            p11 += h2 * pa.w + h3 * pb.w;
        }
#pragma unroll
        for (int o = 1; o <= 2; o <<= 1) {
            p00 += __shfl_xor_sync(0xffffffffu, p00, o);
            p10 += __shfl_xor_sync(0xffffffffu, p10, o);
            p01 += __shfl_xor_sync(0xffffffffu, p01, o);
            p11 += __shfl_xor_sync(0xffffffffu, p11, o);
        }
        if (t4 == 0) {
            {
                float o0 = p00 + b3_0, o1 = p10 + b3_1;
                float pm = tanhf(o0 * isc0) * sc0;
                float pl = tanhf(o1 * isc1) * sc1;
                float zl = z_logstd[b0i * L_ + l], zmn = z_mean[b0i * L_ + l];
                float dmu = zmn - pm;
                float kld = pl - zl + (__expf(2.0f * zl) + dmu * dmu) * 0.5f * __expf(-2.0f * pl) - 0.5f;
                atomicAdd(out + b0i, kld * 0.125f);
            }
            {
                float o0 = p01 + b3_0, o1 = p11 + b3_1;
                float pm = tanhf(o0 * isc0) * sc0;
                float pl = tanhf(o1 * isc1) * sc1;
                float zl = z_logstd[b1i * L_ + l], zmn = z_mean[b1i * L_ + l];
                float dmu = zmn - pm;
                float kld = pl - zl + (__expf(2.0f * zl) + dmu * dmu) * 0.5f * __expf(-2.0f * pl) - 0.5f;
                atomicAdd(out + b1i, kld * 0.125f);
            }
        }
    }
}

extern "C" void kernel_launch(void* const* d_in, const int* in_sizes, int n_in,
                              void* d_out, int out_size) {
    const float* z_sample      = (const float*)d_in[0];
    const int*   target        = (const int*)  d_in[1];
    const float* z_mean        = (const float*)d_in[2];
    const float* z_logstd      = (const float*)d_in[3];
    const float* z_shared      = (const float*)d_in[4];
    const float* u_gumbel      = (const float*)d_in[5];
    const float* u_adj         = (const float*)d_in[6];
    const float* target_params = (const float*)d_in[7];
    const float* enco_theta    = (const float*)d_in[8];
    const float* enco_gamma    = (const float*)d_in[9];
    const float* W1            = (const float*)d_in[10];
    const float* b1            = (const float*)d_in[11];
    const float* gn1_w         = (const float*)d_in[12];
    const float* gn1_b         = (const float*)d_in[13];
    const float* W2            = (const float*)d_in[14];
    const float* b2            = (const float*)d_in[15];
    const float* gn2_w         = (const float*)d_in[16];
    const float* gn2_b         = (const float*)d_in[17];
    const float* W3            = (const float*)d_in[18];
    const float* b3            = (const float*)d_in[19];
    const float* tanh_scale    = (const float*)d_in[20];
    float* out = (float*)d_out;

    prep_kernel<<<B_, 256>>>(target_params, u_gumbel, enco_theta, enco_gamma, u_adj, out);

    cudaFuncSetAttribute(main_kernel, cudaFuncAttributeMaxDynamicSharedMemorySize, SMEM_BYTES);
    main_kernel<<<GRID_MAIN, 256, SMEM_BYTES>>>(
        z_sample, target, z_mean, z_logstd, z_shared,
        W1, b1, gn1_w, gn1_b, W2, b2, gn2_w, gn2_b, W3, b3, tanh_scale, out);
}

// round 12
// speedup vs baseline: 1.2273x; 1.0691x over previous
#include <cuda_runtime.h>
#include <cuda_fp16.h>
#include <math.h>

#define B_   1024
#define L_   32
#define K_   8
#define G_   8
#define C_   128
#define S_   32
#define GRID_MAIN 296
#define NTILES 64
#define NITEMS (L_ * NTILES)

__device__ unsigned char g_ci[B_ * L_];
__device__ unsigned int g_mask[B_ * G_ * L_];

// ---------- helpers ----------
__device__ __forceinline__ unsigned pack2h(float lo, float hi) {
    unsigned r;
    asm("cvt.rn.f16x2.f32 %0, %1, %2;" : "=r"(r) : "f"(hi), "f"(lo));
    return r;
}
__device__ __forceinline__ float silu_f(float x) {
    float h = 0.5f * x, t;
    asm("tanh.approx.f32 %0, %1;" : "=f"(t) : "f"(h));
    return fmaf(h, t, h);
}
__device__ __forceinline__ void mma_f16(float* c,
    unsigned a0, unsigned a1, unsigned a2, unsigned a3, unsigned b0, unsigned b1) {
    asm("mma.sync.aligned.m16n8k16.row.col.f32.f16.f16.f32 "
        "{%0,%1,%2,%3},{%4,%5,%6,%7},{%8,%9},{%0,%1,%2,%3};"
        : "+f"(c[0]), "+f"(c[1]), "+f"(c[2]), "+f"(c[3])
        : "r"(a0), "r"(a1), "r"(a2), "r"(a3), "r"(b0), "r"(b1));
}
__device__ __forceinline__ float bitf(unsigned m, int j) {
    return (float)((m >> j) & 1u);
}
__device__ __forceinline__ float2 ldg2(const float* p) {
    return __ldg((const float2*)p);
}

// Build the 7 k-block fragment halves for one row.
// out[kk][0] = pack(x[db], x[db+1]), out[kk][1] = pack(x[db+8], x[db+9]), db = kk*16 + t4*2.
// Layout: x[0:32)=mask*z, [32:64)=mask, [64:72)=t, [72:104)=z_shared, x[104]=1 (bias), rest 0.
__device__ __forceinline__ void build_row(unsigned Mw, bool tfl, int tgt,
                                          const float* zp, const float* zhp,
                                          int d2, unsigned out[7][2]) {
    // kk0: z region d2, d2+8
    float2 z0 = ldg2(zp + d2);
    float2 z1 = ldg2(zp + d2 + 8);
    out[0][0] = pack2h(bitf(Mw, d2) * z0.x,      bitf(Mw, d2 + 1) * z0.y);
    out[0][1] = pack2h(bitf(Mw, d2 + 8) * z1.x,  bitf(Mw, d2 + 9) * z1.y);
    // kk1: z region d2+16, d2+24
    float2 z2 = ldg2(zp + d2 + 16);
    float2 z3 = ldg2(zp + d2 + 24);
    out[1][0] = pack2h(bitf(Mw, d2 + 16) * z2.x, bitf(Mw, d2 + 17) * z2.y);
    out[1][1] = pack2h(bitf(Mw, d2 + 24) * z3.x, bitf(Mw, d2 + 25) * z3.y);
    // kk2: mask bits j = d2, d2+8
    out[2][0] = pack2h(bitf(Mw, d2),      bitf(Mw, d2 + 1));
    out[2][1] = pack2h(bitf(Mw, d2 + 8),  bitf(Mw, d2 + 9));
    // kk3: mask bits j = d2+16, d2+24
    out[3][0] = pack2h(bitf(Mw, d2 + 16), bitf(Mw, d2 + 17));
    out[3][1] = pack2h(bitf(Mw, d2 + 24), bitf(Mw, d2 + 25));
    // kk4: t flags at k=d2,d2+1 ; z_shared[d2]
    float tv0 = (tfl && tgt == d2)     ? 1.0f : 0.0f;
    float tv1 = (tfl && tgt == d2 + 1) ? 1.0f : 0.0f;
    float2 s0 = ldg2(zhp + d2);
    out[4][0] = pack2h(tv0, tv1);
    out[4][1] = pack2h(s0.x, s0.y);
    // kk5: z_shared[8+d2], [16+d2]
    float2 s1 = ldg2(zhp + 8 + d2);
    float2 s2 = ldg2(zhp + 16 + d2);
    out[5][0] = pack2h(s1.x, s1.y);
    out[5][1] = pack2h(s2.x, s2.y);
    // kk6: z_shared[24+d2] ; bias column d=104 (only t4==0 slot holds 1)
    float2 s3 = ldg2(zhp + 24 + d2);
    out[6][0] = pack2h(s3.x, s3.y);
    out[6][1] = (d2 == 0) ? pack2h(1.0f, 0.0f) : 0u;
}

// ---------- merged prep ----------
__global__ void prep_kernel(const float* __restrict__ tp, const float* __restrict__ ug,
                            const float* __restrict__ th, const float* __restrict__ ga,
                            const float* __restrict__ u_adj, float* __restrict__ out) {
    __shared__ unsigned char sc[L_];
    __shared__ float sep[K_ * K_];
    int b = blockIdx.x, t = threadIdx.x;
    if (t < L_) {
        const float* u = ug + (b * L_ + t) * K_;
        float best = -1e30f; int bi = 0;
#pragma unroll
        for (int k = 0; k < K_; k++) {
            float gum = -logf(-logf(u[k] + 1e-10f) + 1e-10f);
            float v = tp[t * K_ + k] + gum;
            if (v > best) { best = v; bi = k; }
        }
        sc[t] = (unsigned char)bi;
        g_ci[b * L_ + t] = (unsigned char)bi;
    } else if (t >= 64 && t < 128) {
        int e = t - 64;
        float s1 = 1.0f / (1.0f + expf(-th[e]));
        float s2 = 1.0f / (1.0f + expf(-ga[e]));
        sep[e] = s1 * s2;
    }
    if (t == 0) out[b] = 0.0f;
    __syncthreads();
    int g = t >> 5, l = t & 31;
    int cl = sc[l];
    unsigned bits = 0;
#pragma unroll
    for (int cj = 0; cj < K_; cj++) {
        float u = u_adj[((b * G_ + g) * K_ + cj) * K_ + cl];
        bits |= (u < sep[cj * K_ + cl]) ? (1u << cj) : 0u;
    }
    unsigned wv = 0;
#pragma unroll
    for (int j = 0; j < L_; j++) {
        unsigned mj = (bits >> sc[j]) & 1u;
        if (j == l) mj = 0;
        wv |= mj << j;
    }
    g_mask[(b * G_ + g) * L_ + l] = wv;
}

// ---------- smem layout (bytes) ----------
// W1/W2: 128 rows x 320B (stride 320 == 64 mod 128 -> conflict-free per 8-lane phase)
#define OFF_W1   0
#define OFF_W2   40960
#define OFF_WB1  81920
#define OFF_B2   82944
#define OFF_P2   83456
#define SMEM_BYTES 85504

__global__ __launch_bounds__(256, 2) void main_kernel(
    const float* __restrict__ z_sample, const int* __restrict__ target,
    const float* __restrict__ z_mean,   const float* __restrict__ z_logstd,
    const float* __restrict__ z_shared,
    const float* __restrict__ W1, const float* __restrict__ b1g,
    const float* __restrict__ g1wg, const float* __restrict__ g1bg,
    const float* __restrict__ W2, const float* __restrict__ b2g,
    const float* __restrict__ g2wg, const float* __restrict__ g2bg,
    const float* __restrict__ W3g, const float* __restrict__ b3g,
    const float* __restrict__ tsc, float* __restrict__ out)
{
    extern __shared__ char smem[];
    uint2*  W1u2 = (uint2*)(smem + OFF_W1);
    uint2*  W2u2 = (uint2*)(smem + OFF_W2);
    const uint4* W1q4 = (const uint4*)(smem + OFF_W1);
    const uint4* W2q4 = (const uint4*)(smem + OFF_W2);
    float4* sWB1 = (float4*)(smem + OFF_WB1);   // (g1w[c0],g1b[c0],g1w[c0+1],g1b[c0+1])
    float2* sB2  = (float2*)(smem + OFF_B2);    // b2 channel pairs
    float4* sP2  = (float4*)(smem + OFF_P2);    // (g2w,g2b,w3_0,w3_1) per channel

    const int tid = threadIdx.x;
    const int wid = tid >> 5;
    const int lane = tid & 31;
    const int gid = lane >> 2;
    const int t4 = lane & 3;
    const int d2 = t4 * 2;

    const int start = (int)(((long long)blockIdx.x * NITEMS) / GRID_MAIN);
    const int end   = (int)(((long long)(blockIdx.x + 1) * NITEMS) / GRID_MAIN);

    int cur_l = -1;
    float b3_0 = 0.f, b3_1 = 0.f, sc0 = 1.f, sc1 = 1.f, isc0 = 1.f, isc1 = 1.f;

    for (int item = start; item < end; item++) {
        const int l = item >> 6;
        const int tile = item & 63;

        if (l != cur_l) {
            __syncthreads();
            const float* W1g = W1 + l * C_ * 104;
            for (int idx = tid; idx < 128 * 32; idx += 256) {
                int c = idx >> 5, s = idx & 31;
                int kk = s >> 2, tq = s & 3;
                int d0 = kk * 16 + tq * 2, d1 = d0 + 8;
                // fold b1 into the d=104 constant-1 column
                float w00 = (d0 < 104) ? W1g[c * 104 + d0]
                                       : ((d0 == 104) ? b1g[l * C_ + c] : 0.0f);
                float w01 = (d0 + 1 < 104) ? W1g[c * 104 + d0 + 1] : 0.0f;
                float w10 = (d1 < 104) ? W1g[c * 104 + d1]
                                       : ((d1 == 104) ? b1g[l * C_ + c] : 0.0f);
                float w11 = (d1 + 1 < 104) ? W1g[c * 104 + d1 + 1] : 0.0f;
                W1u2[c * 40 + (kk >> 1) * 8 + tq * 2 + (kk & 1)] =
                    make_uint2(pack2h(w00, w01), pack2h(w10, w11));
            }
            const float* W2g = W2 + l * C_ * C_;
            for (int idx = tid; idx < 128 * 32; idx += 256) {
                int c = idx >> 5, s = idx & 31;
                int kk = s >> 2, tq = s & 3;
                int d0 = kk * 16 + tq * 2, d1 = d0 + 8;
                W2u2[c * 40 + (kk >> 1) * 8 + tq * 2 + (kk & 1)] =
                    make_uint2(pack2h(W2g[c * C_ + d0], W2g[c * C_ + d0 + 1]),
                               pack2h(W2g[c * C_ + d1], W2g[c * C_ + d1 + 1]));
            }
            if (tid < 64) {
                int c0 = 2 * tid;
                sWB1[tid] = make_float4(g1wg[l * C_ + c0], g1bg[l * C_ + c0],
                                        g1wg[l * C_ + c0 + 1], g1bg[l * C_ + c0 + 1]);
                sB2[tid]  = make_float2(b2g[l * C_ + c0], b2g[l * C_ + c0 + 1]);
            }
            if (tid < 128) {
                sP2[tid] = make_float4(g2wg[l * C_ + tid], g2bg[l * C_ + tid],
                                       W3g[l * 2 * C_ + tid], W3g[l * 2 * C_ + C_ + tid]);
            }
            b3_0 = b3g[l * 2]; b3_1 = b3g[l * 2 + 1];
            sc0 = __expf(tsc[l * 2]); sc1 = __expf(tsc[l * 2 + 1]);
            isc0 = 1.0f / sc0; isc1 = 1.0f / sc1;
            __syncthreads();
            cur_l = l;
        }

        // per-thread rows: r0 = wid*16+gid (batch b0), r1 = r0+8 (batch b1)
        const int grow0 = tile * 128 + wid * 16 + gid;
        const int grow1 = grow0 + 8;
        const int b0i = grow0 >> 3, b1i = grow1 >> 3;
        const unsigned Mw0 = __ldg(&g_mask[grow0 * L_ + l]);
        const unsigned Mw1 = __ldg(&g_mask[grow1 * L_ + l]);
        const int tgt0 = __ldg(&target[b0i]), tgt1 = __ldg(&target[b1i]);
        const bool tf0 = (g_ci[b0i * L_ + l] == tgt0);
        const bool tf1 = (g_ci[b1i * L_ + l] == tgt1);

        // ---- build A1 fragments directly from global (L1/L2-hot) ----
        unsigned Ah[7][4];
        {
            unsigned rA[7][2], rB[7][2];
            build_row(Mw0, tf0, tgt0, z_sample + b0i * L_, z_shared + b0i * S_, d2, rA);
            build_row(Mw1, tf1, tgt1, z_sample + b1i * L_, z_shared + b1i * S_, d2, rB);
#pragma unroll
            for (int kk = 0; kk < 7; kk++) {
                Ah[kk][0] = rA[kk][0];
                Ah[kk][1] = rB[kk][0];
                Ah[kk][2] = rA[kk][1];
                Ah[kk][3] = rB[kk][1];
            }
        }

        // ---- MMA1 (bias folded into W1) ----
        float acc[16][4];
#pragma unroll
        for (int nt = 0; nt < 16; nt++)
#pragma unroll
            for (int i = 0; i < 4; i++) acc[nt][i] = 0.0f;

#pragma unroll
        for (int nt = 0; nt < 16; nt++) {
            const uint4* bp = W1q4 + (nt * 8 + gid) * 20 + t4;
#pragma unroll
            for (int j = 0; j < 4; j++) {
                uint4 bq = bp[j * 4];
                mma_f16(acc[nt], Ah[2*j][0], Ah[2*j][1], Ah[2*j][2], Ah[2*j][3], bq.x, bq.y);
                if (j < 3)
                    mma_f16(acc[nt], Ah[2*j+1][0], Ah[2*j+1][1], Ah[2*j+1][2], Ah[2*j+1][3], bq.z, bq.w);
            }
        }

        // ---- GN1 + SiLU -> A2 fragments ----
        float s0 = 0.f, q0 = 0.f, s1 = 0.f, q1 = 0.f;
#pragma unroll
        for (int nt = 0; nt < 16; nt++) {
            s0 += acc[nt][0] + acc[nt][1];
            q0 += acc[nt][0] * acc[nt][0] + acc[nt][1] * acc[nt][1];
            s1 += acc[nt][2] + acc[nt][3];
            q1 += acc[nt][2] * acc[nt][2] + acc[nt][3] * acc[nt][3];
        }
#pragma unroll
        for (int o = 1; o <= 2; o <<= 1) {
            s0 += __shfl_xor_sync(0xffffffffu, s0, o);
            q0 += __shfl_xor_sync(0xffffffffu, q0, o);
            s1 += __shfl_xor_sync(0xffffffffu, s1, o);
            q1 += __shfl_xor_sync(0xffffffffu, q1, o);
        }
        float mu0 = s0 * (1.0f / 128.0f);
        float inv0 = rsqrtf(q0 * (1.0f / 128.0f) - mu0 * mu0 + 1e-5f);
        float mu1 = s1 * (1.0f / 128.0f);
        float inv1 = rsqrtf(q1 * (1.0f / 128.0f) - mu1 * mu1 + 1e-5f);

        unsigned A2h[8][4];
#pragma unroll
        for (int kk = 0; kk < 8; kk++) {
            int nt0 = 2 * kk, nt1 = 2 * kk + 1;
            float4 wb0 = sWB1[nt0 * 4 + t4];
            float4 wb1 = sWB1[nt1 * 4 + t4];
            float h00 = silu_f((acc[nt0][0] - mu0) * inv0 * wb0.x + wb0.y);
            float h01 = silu_f((acc[nt0][1] - mu0) * inv0 * wb0.z + wb0.w);
            float h02 = silu_f((acc[nt0][2] - mu1) * inv1 * wb0.x + wb0.y);
            float h03 = silu_f((acc[nt0][3] - mu1) * inv1 * wb0.z + wb0.w);
            float h10 = silu_f((acc[nt1][0] - mu0) * inv0 * wb1.x + wb1.y);
            float h11 = silu_f((acc[nt1][1] - mu0) * inv0 * wb1.z + wb1.w);
            float h12 = silu_f((acc[nt1][2] - mu1) * inv1 * wb1.x + wb1.y);
            float h13 = silu_f((acc[nt1][3] - mu1) * inv1 * wb1.z + wb1.w);
            A2h[kk][0] = pack2h(h00, h01);
            A2h[kk][1] = pack2h(h02, h03);
            A2h[kk][2] = pack2h(h10, h11);
            A2h[kk][3] = pack2h(h12, h13);
        }

        // ---- MMA2 ----
#pragma unroll
        for (int nt = 0; nt < 16; nt++)
#pragma unroll
            for (int i = 0; i < 4; i++) acc[nt][i] = 0.0f;

#pragma unroll
        for (int nt = 0; nt < 16; nt++) {
            const uint4* bp = W2q4 + (nt * 8 + gid) * 20 + t4;
#pragma unroll
            for (int j = 0; j < 4; j++) {
                uint4 bq = bp[j * 4];
                mma_f16(acc[nt], A2h[2*j][0], A2h[2*j][1], A2h[2*j][2], A2h[2*j][3], bq.x, bq.y);
                mma_f16(acc[nt], A2h[2*j+1][0], A2h[2*j+1][1], A2h[2*j+1][2], A2h[2*j+1][3], bq.z, bq.w);
            }
        }

        // ---- GN2 + SiLU + layer3 + KL ----
        s0 = 0.f; q0 = 0.f; s1 = 0.f; q1 = 0.f;
#pragma unroll
        for (int nt = 0; nt < 16; nt++) {
            float2 bb = sB2[nt * 4 + t4];
            acc[nt][0] += bb.x; acc[nt][1] += bb.y;
            acc[nt][2] += bb.x; acc[nt][3] += bb.y;
            s0 += acc[nt][0] + acc[nt][1];
            q0 += acc[nt][0] * acc[nt][0] + acc[nt][1] * acc[nt][1];
            s1 += acc[nt][2] + acc[nt][3];
            q1 += acc[nt][2] * acc[nt][2] + acc[nt][3] * acc[nt][3];
        }
#pragma unroll
        for (int o = 1; o <= 2; o <<= 1) {
            s0 += __shfl_xor_sync(0xffffffffu, s0, o);
            q0 += __shfl_xor_sync(0xffffffffu, q0, o);
            s1 += __shfl_xor_sync(0xffffffffu, s1, o);
            q1 += __shfl_xor_sync(0xffffffffu, q1, o);
        }
        mu0 = s0 * (1.0f / 128.0f);
        inv0 = rsqrtf(q0 * (1.0f / 128.0f) - mu0 * mu0 + 1e-5f);
        mu1 = s1 * (1.0f / 128.0f);
        inv1 = rsqrtf(q1 * (1.0f / 128.0f) - mu1 * mu1 + 1e-5f);

        float p00 = 0.f, p10 = 0.f, p01 = 0.f, p11 = 0.f;
#pragma unroll
        for (int nt = 0; nt < 16; nt++) {
            float4 pa = sP2[nt * 8 + 2 * t4];
            float4 pb = sP2[nt * 8 + 2 * t4 + 1];
            float h0 = silu_f((acc[nt][0] - mu0) * inv0 * pa.x + pa.y);
            float h1 = silu_f((acc[nt][1] - mu0) * inv0 * pb.x + pb.y);
            float h2 = silu_f((acc[nt][2] - mu1) * inv1 * pa.x + pa.y);
            float h3 = silu_f((acc[nt][3] - mu1) * inv1 * pb.x + pb.y);
            p00 += h0 * pa.z + h1 * pb.z;
            p10 += h0 * pa.w + h1 * pb.w;
            p01 += h2 * pa.z + h3 * pb.z;
            p11 += h2 * pa.w + h3 * pb.w;
        }
#pragma unroll
        for (int o = 1; o <= 2; o <<= 1) {
            p00 += __shfl_xor_sync(0xffffffffu, p00, o);
            p10 += __shfl_xor_sync(0xffffffffu, p10, o);
            p01 += __shfl_xor_sync(0xffffffffu, p01, o);
            p11 += __shfl_xor_sync(0xffffffffu, p11, o);
        }
        if (t4 == 0) {
            {
                float o0 = p00 + b3_0, o1 = p10 + b3_1;
                float pm = tanhf(o0 * isc0) * sc0;
                float pl = tanhf(o1 * isc1) * sc1;
                float zl = z_logstd[b0i * L_ + l], zmn = z_mean[b0i * L_ + l];
                float dmu = zmn - pm;
                float kld = pl - zl + (__expf(2.0f * zl) + dmu * dmu) * 0.5f * __expf(-2.0f * pl) - 0.5f;
                atomicAdd(out + b0i, kld * 0.125f);
            }
            {
                float o0 = p01 + b3_0, o1 = p11 + b3_1;
                float pm = tanhf(o0 * isc0) * sc0;
                float pl = tanhf(o1 * isc1) * sc1;
                float zl = z_logstd[b1i * L_ + l], zmn = z_mean[b1i * L_ + l];
                float dmu = zmn - pm;
                float kld = pl - zl + (__expf(2.0f * zl) + dmu * dmu) * 0.5f * __expf(-2.0f * pl) - 0.5f;
                atomicAdd(out + b1i, kld * 0.125f);
            }
        }
    }
}

extern "C" void kernel_launch(void* const* d_in, const int* in_sizes, int n_in,
                              void* d_out, int out_size) {
    const float* z_sample      = (const float*)d_in[0];
    const int*   target        = (const int*)  d_in[1];
    const float* z_mean        = (const float*)d_in[2];
    const float* z_logstd      = (const float*)d_in[3];
    const float* z_shared      = (const float*)d_in[4];
    const float* u_gumbel      = (const float*)d_in[5];
    const float* u_adj         = (const float*)d_in[6];
    const float* target_params = (const float*)d_in[7];
    const float* enco_theta    = (const float*)d_in[8];
    const float* enco_gamma    = (const float*)d_in[9];
    const float* W1            = (const float*)d_in[10];
    const float* b1            = (const float*)d_in[11];
    const float* gn1_w         = (const float*)d_in[12];
    const float* gn1_b         = (const float*)d_in[13];
    const float* W2            = (const float*)d_in[14];
    const float* b2            = (const float*)d_in[15];
    const float* gn2_w         = (const float*)d_in[16];
    const float* gn2_b         = (const float*)d_in[17];
    const float* W3            = (const float*)d_in[18];
    const float* b3            = (const float*)d_in[19];
    const float* tanh_scale    = (const float*)d_in[20];
    float* out = (float*)d_out;

    prep_kernel<<<B_, 256>>>(target_params, u_gumbel, enco_theta, enco_gamma, u_adj, out);

    cudaFuncSetAttribute(main_kernel, cudaFuncAttributeMaxDynamicSharedMemorySize, SMEM_BYTES);
    main_kernel<<<GRID_MAIN, 256, SMEM_BYTES>>>(
        z_sample, target, z_mean, z_logstd, z_shared,
        W1, b1, gn1_w, gn1_b, W2, b2, gn2_w, gn2_b, W3, b3, tanh_scale, out);
}

// round 13
// speedup vs baseline: 1.2616x; 1.0280x over previous
#include <cuda_runtime.h>
#include <cuda_fp16.h>
#include <math.h>

#define B_   1024
#define L_   32
#define K_   8
#define G_   8
#define C_   128
#define S_   32
#define GRID_MAIN 296
#define NTILES 64
#define NITEMS (L_ * NTILES)

__device__ unsigned char g_ci[B_ * L_];
__device__ unsigned int g_mask[B_ * G_ * L_];

// ---------- helpers ----------
__device__ __forceinline__ unsigned pack2h(float lo, float hi) {
    unsigned r;
    asm("cvt.rn.f16x2.f32 %0, %1, %2;" : "=r"(r) : "f"(hi), "f"(lo));
    return r;
}
__device__ __forceinline__ __half2 u2h(unsigned u) { return *reinterpret_cast<__half2*>(&u); }
__device__ __forceinline__ unsigned h2u(__half2 h) { return *reinterpret_cast<unsigned*>(&h); }

__device__ __forceinline__ float silu_f(float x) {
    float h = 0.5f * x, t;
    asm("tanh.approx.f32 %0, %1;" : "=f"(t) : "f"(h));
    return fmaf(h, t, h);
}
// packed GN + SiLU: v,mu,inv,w,b all f16x2; returns silu((v-mu)*inv*w+b) packed
__device__ __forceinline__ unsigned gnsilu2(unsigned v, unsigned mu2, unsigned inv2,
                                            unsigned w2, unsigned b2) {
    __half2 x = __hsub2(u2h(v), u2h(mu2));
    x = __hmul2(x, u2h(inv2));
    x = __hfma2(x, u2h(w2), u2h(b2));
    __half2 m = __hmul2(x, __float2half2_rn(0.5f));
    unsigned t;
    asm("tanh.approx.f16x2 %0, %1;" : "=r"(t) : "r"(h2u(m)));
    return h2u(__hfma2(m, u2h(t), m));
}
__device__ __forceinline__ void mma_f16(float* c,
    unsigned a0, unsigned a1, unsigned a2, unsigned a3, unsigned b0, unsigned b1) {
    asm("mma.sync.aligned.m16n8k16.row.col.f32.f16.f16.f32 "
        "{%0,%1,%2,%3},{%4,%5,%6,%7},{%8,%9},{%0,%1,%2,%3};"
        : "+f"(c[0]), "+f"(c[1]), "+f"(c[2]), "+f"(c[3])
        : "r"(a0), "r"(a1), "r"(a2), "r"(a3), "r"(b0), "r"(b1));
}
__device__ __forceinline__ float bitf(unsigned m, int j) {
    return (float)((m >> j) & 1u);
}
__device__ __forceinline__ float2 ldg2(const float* p) {
    return __ldg((const float2*)p);
}

// Build the 7 k-block fragment halves for one row (see round-12 layout).
__device__ __forceinline__ void build_row(unsigned Mw, bool tfl, int tgt,
                                          const float* zp, const float* zhp,
                                          int d2, unsigned out[7][2]) {
    float2 z0 = ldg2(zp + d2);
    float2 z1 = ldg2(zp + d2 + 8);
    out[0][0] = pack2h(bitf(Mw, d2) * z0.x,      bitf(Mw, d2 + 1) * z0.y);
    out[0][1] = pack2h(bitf(Mw, d2 + 8) * z1.x,  bitf(Mw, d2 + 9) * z1.y);
    float2 z2 = ldg2(zp + d2 + 16);
    float2 z3 = ldg2(zp + d2 + 24);
    out[1][0] = pack2h(bitf(Mw, d2 + 16) * z2.x, bitf(Mw, d2 + 17) * z2.y);
    out[1][1] = pack2h(bitf(Mw, d2 + 24) * z3.x, bitf(Mw, d2 + 25) * z3.y);
    out[2][0] = pack2h(bitf(Mw, d2),      bitf(Mw, d2 + 1));
    out[2][1] = pack2h(bitf(Mw, d2 + 8),  bitf(Mw, d2 + 9));
    out[3][0] = pack2h(bitf(Mw, d2 + 16), bitf(Mw, d2 + 17));
    out[3][1] = pack2h(bitf(Mw, d2 + 24), bitf(Mw, d2 + 25));
    float tv0 = (tfl && tgt == d2)     ? 1.0f : 0.0f;
    float tv1 = (tfl && tgt == d2 + 1) ? 1.0f : 0.0f;
    float2 s0 = ldg2(zhp + d2);
    out[4][0] = pack2h(tv0, tv1);
    out[4][1] = pack2h(s0.x, s0.y);
    float2 s1 = ldg2(zhp + 8 + d2);
    float2 s2 = ldg2(zhp + 16 + d2);
    out[5][0] = pack2h(s1.x, s1.y);
    out[5][1] = pack2h(s2.x, s2.y);
    float2 s3 = ldg2(zhp + 24 + d2);
    out[6][0] = pack2h(s3.x, s3.y);
    out[6][1] = (d2 == 0) ? pack2h(1.0f, 0.0f) : 0u;
}

// ---------- merged prep ----------
__global__ void prep_kernel(const float* __restrict__ tp, const float* __restrict__ ug,
                            const float* __restrict__ th, const float* __restrict__ ga,
                            const float* __restrict__ u_adj, float* __restrict__ out) {
    __shared__ unsigned char sc[L_];
    __shared__ float sep[K_ * K_];
    int b = blockIdx.x, t = threadIdx.x;
    if (t < L_) {
        const float* u = ug + (b * L_ + t) * K_;
        float best = -1e30f; int bi = 0;
#pragma unroll
        for (int k = 0; k < K_; k++) {
            float gum = -logf(-logf(u[k] + 1e-10f) + 1e-10f);
            float v = tp[t * K_ + k] + gum;
            if (v > best) { best = v; bi = k; }
        }
        sc[t] = (unsigned char)bi;
        g_ci[b * L_ + t] = (unsigned char)bi;
    } else if (t >= 64 && t < 128) {
        int e = t - 64;
        float s1 = 1.0f / (1.0f + expf(-th[e]));
        float s2 = 1.0f / (1.0f + expf(-ga[e]));
        sep[e] = s1 * s2;
    }
    if (t == 0) out[b] = 0.0f;
    __syncthreads();
    int g = t >> 5, l = t & 31;
    int cl = sc[l];
    unsigned bits = 0;
#pragma unroll
    for (int cj = 0; cj < K_; cj++) {
        float u = u_adj[((b * G_ + g) * K_ + cj) * K_ + cl];
        bits |= (u < sep[cj * K_ + cl]) ? (1u << cj) : 0u;
    }
    unsigned wv = 0;
#pragma unroll
    for (int j = 0; j < L_; j++) {
        unsigned mj = (bits >> sc[j]) & 1u;
        if (j == l) mj = 0;
        wv |= mj << j;
    }
    g_mask[(b * G_ + g) * L_ + l] = wv;
}

// ---------- smem layout (bytes) ----------
#define OFF_W1    0
#define OFF_W2    40960
#define OFF_WB1H  81920   // uint2[64]: (g1w pair f16x2, g1b pair f16x2)
#define OFF_P2H   82432   // uint2[64]: (g2w pair f16x2, g2b pair f16x2)
#define OFF_B2    82944   // float2[64]: b2 pairs fp32
#define OFF_W3    83456   // float4[64]: (w30_c0, w31_c0, w30_c1, w31_c1)
#define SMEM_BYTES 84480

__global__ __launch_bounds__(256, 2) void main_kernel(
    const float* __restrict__ z_sample, const int* __restrict__ target,
    const float* __restrict__ z_mean,   const float* __restrict__ z_logstd,
    const float* __restrict__ z_shared,
    const float* __restrict__ W1, const float* __restrict__ b1g,
    const float* __restrict__ g1wg, const float* __restrict__ g1bg,
    const float* __restrict__ W2, const float* __restrict__ b2g,
    const float* __restrict__ g2wg, const float* __restrict__ g2bg,
    const float* __restrict__ W3g, const float* __restrict__ b3g,
    const float* __restrict__ tsc, float* __restrict__ out)
{
    extern __shared__ char smem[];
    uint2*  W1u2 = (uint2*)(smem + OFF_W1);
    uint2*  W2u2 = (uint2*)(smem + OFF_W2);
    const uint4* W1q4 = (const uint4*)(smem + OFF_W1);
    const uint4* W2q4 = (const uint4*)(smem + OFF_W2);
    uint2*  sWB1h = (uint2*)(smem + OFF_WB1H);
    uint2*  sP2h  = (uint2*)(smem + OFF_P2H);
    float2* sB2   = (float2*)(smem + OFF_B2);
    float4* sW3   = (float4*)(smem + OFF_W3);

    const int tid = threadIdx.x;
    const int wid = tid >> 5;
    const int lane = tid & 31;
    const int gid = lane >> 2;
    const int t4 = lane & 3;
    const int d2 = t4 * 2;

    const int start = (int)(((long long)blockIdx.x * NITEMS) / GRID_MAIN);
    const int end   = (int)(((long long)(blockIdx.x + 1) * NITEMS) / GRID_MAIN);

    int cur_l = -1;
    float b3_0 = 0.f, b3_1 = 0.f, sc0 = 1.f, sc1 = 1.f, isc0 = 1.f, isc1 = 1.f;

    for (int item = start; item < end; item++) {
        const int l = item >> 6;
        const int tile = item & 63;

        if (l != cur_l) {
            __syncthreads();
            const float* W1g = W1 + l * C_ * 104;
            for (int idx = tid; idx < 128 * 32; idx += 256) {
                int c = idx >> 5, s = idx & 31;
                int kk = s >> 2, tq = s & 3;
                int d0 = kk * 16 + tq * 2, d1 = d0 + 8;
                float w00 = (d0 < 104) ? W1g[c * 104 + d0]
                                       : ((d0 == 104) ? b1g[l * C_ + c] : 0.0f);
                float w01 = (d0 + 1 < 104) ? W1g[c * 104 + d0 + 1] : 0.0f;
                float w10 = (d1 < 104) ? W1g[c * 104 + d1]
                                       : ((d1 == 104) ? b1g[l * C_ + c] : 0.0f);
                float w11 = (d1 + 1 < 104) ? W1g[c * 104 + d1 + 1] : 0.0f;
                W1u2[c * 40 + (kk >> 1) * 8 + tq * 2 + (kk & 1)] =
                    make_uint2(pack2h(w00, w01), pack2h(w10, w11));
            }
            const float* W2g = W2 + l * C_ * C_;
            for (int idx = tid; idx < 128 * 32; idx += 256) {
                int c = idx >> 5, s = idx & 31;
                int kk = s >> 2, tq = s & 3;
                int d0 = kk * 16 + tq * 2, d1 = d0 + 8;
                W2u2[c * 40 + (kk >> 1) * 8 + tq * 2 + (kk & 1)] =
                    make_uint2(pack2h(W2g[c * C_ + d0], W2g[c * C_ + d0 + 1]),
                               pack2h(W2g[c * C_ + d1], W2g[c * C_ + d1 + 1]));
            }
            if (tid < 64) {
                int c0 = 2 * tid;
                sWB1h[tid] = make_uint2(pack2h(g1wg[l * C_ + c0], g1wg[l * C_ + c0 + 1]),
                                        pack2h(g1bg[l * C_ + c0], g1bg[l * C_ + c0 + 1]));
                sP2h[tid]  = make_uint2(pack2h(g2wg[l * C_ + c0], g2wg[l * C_ + c0 + 1]),
                                        pack2h(g2bg[l * C_ + c0], g2bg[l * C_ + c0 + 1]));
                sB2[tid]   = make_float2(b2g[l * C_ + c0], b2g[l * C_ + c0 + 1]);
                sW3[tid]   = make_float4(W3g[l * 2 * C_ + c0],     W3g[l * 2 * C_ + C_ + c0],
                                         W3g[l * 2 * C_ + c0 + 1], W3g[l * 2 * C_ + C_ + c0 + 1]);
            }
            b3_0 = b3g[l * 2]; b3_1 = b3g[l * 2 + 1];
            sc0 = __expf(tsc[l * 2]); sc1 = __expf(tsc[l * 2 + 1]);
            isc0 = 1.0f / sc0; isc1 = 1.0f / sc1;
            __syncthreads();
            cur_l = l;
        }

        // per-thread rows: r0 = wid*16+gid (batch b0), r1 = r0+8 (batch b1)
        const int grow0 = tile * 128 + wid * 16 + gid;
        const int grow1 = grow0 + 8;
        const int b0i = grow0 >> 3, b1i = grow1 >> 3;
        const unsigned Mw0 = __ldg(&g_mask[grow0 * L_ + l]);
        const unsigned Mw1 = __ldg(&g_mask[grow1 * L_ + l]);
        const int tgt0 = __ldg(&target[b0i]), tgt1 = __ldg(&target[b1i]);
        const bool tf0 = (g_ci[b0i * L_ + l] == tgt0);
        const bool tf1 = (g_ci[b1i * L_ + l] == tgt1);

        // ---- build A1 fragments from global (L1/L2-hot) ----
        unsigned Ah[7][4];
        {
            unsigned rA[7][2], rB[7][2];
            build_row(Mw0, tf0, tgt0, z_sample + b0i * L_, z_shared + b0i * S_, d2, rA);
            build_row(Mw1, tf1, tgt1, z_sample + b1i * L_, z_shared + b1i * S_, d2, rB);
#pragma unroll
            for (int kk = 0; kk < 7; kk++) {
                Ah[kk][0] = rA[kk][0];
                Ah[kk][1] = rB[kk][0];
                Ah[kk][2] = rA[kk][1];
                Ah[kk][3] = rB[kk][1];
            }
        }

        // ---- MMA1 (bias folded into W1) ----
        float acc[16][4];
#pragma unroll
        for (int nt = 0; nt < 16; nt++)
#pragma unroll
            for (int i = 0; i < 4; i++) acc[nt][i] = 0.0f;

#pragma unroll
        for (int nt = 0; nt < 16; nt++) {
            const uint4* bp = W1q4 + (nt * 8 + gid) * 20 + t4;
#pragma unroll
            for (int j = 0; j < 4; j++) {
                uint4 bq = bp[j * 4];
                mma_f16(acc[nt], Ah[2*j][0], Ah[2*j][1], Ah[2*j][2], Ah[2*j][3], bq.x, bq.y);
                if (j < 3)
                    mma_f16(acc[nt], Ah[2*j+1][0], Ah[2*j+1][1], Ah[2*j+1][2], Ah[2*j+1][3], bq.z, bq.w);
            }
        }

        // ---- GN1 stats (fp32) ----
        float s0 = 0.f, q0 = 0.f, s1 = 0.f, q1 = 0.f;
#pragma unroll
        for (int nt = 0; nt < 16; nt++) {
            s0 += acc[nt][0] + acc[nt][1];
            q0 += acc[nt][0] * acc[nt][0] + acc[nt][1] * acc[nt][1];
            s1 += acc[nt][2] + acc[nt][3];
            q1 += acc[nt][2] * acc[nt][2] + acc[nt][3] * acc[nt][3];
        }
#pragma unroll
        for (int o = 1; o <= 2; o <<= 1) {
            s0 += __shfl_xor_sync(0xffffffffu, s0, o);
            q0 += __shfl_xor_sync(0xffffffffu, q0, o);
            s1 += __shfl_xor_sync(0xffffffffu, s1, o);
            q1 += __shfl_xor_sync(0xffffffffu, q1, o);
        }
        float mu0 = s0 * (1.0f / 128.0f);
        float inv0 = rsqrtf(q0 * (1.0f / 128.0f) - mu0 * mu0 + 1e-5f);
        float mu1 = s1 * (1.0f / 128.0f);
        float inv1 = rsqrtf(q1 * (1.0f / 128.0f) - mu1 * mu1 + 1e-5f);

        // ---- GN1 + SiLU in packed f16x2 -> A2 fragments ----
        unsigned mu2_0 = pack2h(mu0, mu0), mu2_1 = pack2h(mu1, mu1);
        unsigned iv2_0 = pack2h(inv0, inv0), iv2_1 = pack2h(inv1, inv1);
        unsigned A2h[8][4];
#pragma unroll
        for (int kk = 0; kk < 8; kk++) {
            int nt0 = 2 * kk, nt1 = 2 * kk + 1;
            uint2 wb0 = sWB1h[nt0 * 4 + t4];
            uint2 wb1 = sWB1h[nt1 * 4 + t4];
            A2h[kk][0] = gnsilu2(pack2h(acc[nt0][0], acc[nt0][1]), mu2_0, iv2_0, wb0.x, wb0.y);
            A2h[kk][1] = gnsilu2(pack2h(acc[nt0][2], acc[nt0][3]), mu2_1, iv2_1, wb0.x, wb0.y);
            A2h[kk][2] = gnsilu2(pack2h(acc[nt1][0], acc[nt1][1]), mu2_0, iv2_0, wb1.x, wb1.y);
            A2h[kk][3] = gnsilu2(pack2h(acc[nt1][2], acc[nt1][3]), mu2_1, iv2_1, wb1.x, wb1.y);
        }

        // ---- MMA2 ----
#pragma unroll
        for (int nt = 0; nt < 16; nt++)
#pragma unroll
            for (int i = 0; i < 4; i++) acc[nt][i] = 0.0f;

#pragma unroll
        for (int nt = 0; nt < 16; nt++) {
            const uint4* bp = W2q4 + (nt * 8 + gid) * 20 + t4;
#pragma unroll
            for (int j = 0; j < 4; j++) {
                uint4 bq = bp[j * 4];
                mma_f16(acc[nt], A2h[2*j][0], A2h[2*j][1], A2h[2*j][2], A2h[2*j][3], bq.x, bq.y);
                mma_f16(acc[nt], A2h[2*j+1][0], A2h[2*j+1][1], A2h[2*j+1][2], A2h[2*j+1][3], bq.z, bq.w);
            }
        }

        // ---- GN2 stats (fp32, b2 added first) ----
        s0 = 0.f; q0 = 0.f; s1 = 0.f; q1 = 0.f;
#pragma unroll
        for (int nt = 0; nt < 16; nt++) {
            float2 bb = sB2[nt * 4 + t4];
            acc[nt][0] += bb.x; acc[nt][1] += bb.y;
            acc[nt][2] += bb.x; acc[nt][3] += bb.y;
            s0 += acc[nt][0] + acc[nt][1];
            q0 += acc[nt][0] * acc[nt][0] + acc[nt][1] * acc[nt][1];
            s1 += acc[nt][2] + acc[nt][3];
            q1 += acc[nt][2] * acc[nt][2] + acc[nt][3] * acc[nt][3];
        }
#pragma unroll
        for (int o = 1; o <= 2; o <<= 1) {
            s0 += __shfl_xor_sync(0xffffffffu, s0, o);
            q0 += __shfl_xor_sync(0xffffffffu, q0, o);
            s1 += __shfl_xor_sync(0xffffffffu, s1, o);
            q1 += __shfl_xor_sync(0xffffffffu, q1, o);
        }
        mu0 = s0 * (1.0f / 128.0f);
        inv0 = rsqrtf(q0 * (1.0f / 128.0f) - mu0 * mu0 + 1e-5f);
        mu1 = s1 * (1.0f / 128.0f);
        inv1 = rsqrtf(q1 * (1.0f / 128.0f) - mu1 * mu1 + 1e-5f);
        mu2_0 = pack2h(mu0, mu0); mu2_1 = pack2h(mu1, mu1);
        iv2_0 = pack2h(inv0, inv0); iv2_1 = pack2h(inv1, inv1);

        // ---- GN2 + SiLU (f16x2) + W3 dot (fp32) + KL ----
        float p00 = 0.f, p10 = 0.f, p01 = 0.f, p11 = 0.f;
#pragma unroll
        for (int nt = 0; nt < 16; nt++) {
            uint2 wb = sP2h[nt * 4 + t4];
            float4 w3 = sW3[nt * 4 + t4];  // (w30_c0, w31_c0, w30_c1, w31_c1)
            float2 ha = __half22float2(u2h(
                gnsilu2(pack2h(acc[nt][0], acc[nt][1]), mu2_0, iv2_0, wb.x, wb.y)));
            float2 hb = __half22float2(u2h(
                gnsilu2(pack2h(acc[nt][2], acc[nt][3]), mu2_1, iv2_1, wb.x, wb.y)));
            p00 += ha.x * w3.x + ha.y * w3.z;
            p10 += ha.x * w3.y + ha.y * w3.w;
            p01 += hb.x * w3.x + hb.y * w3.z;
            p11 += hb.x * w3.y + hb.y * w3.w;
        }
#pragma unroll
        for (int o = 1; o <= 2; o <<= 1) {
            p00 += __shfl_xor_sync(0xffffffffu, p00, o);
            p10 += __shfl_xor_sync(0xffffffffu, p10, o);
            p01 += __shfl_xor_sync(0xffffffffu, p01, o);
            p11 += __shfl_xor_sync(0xffffffffu, p11, o);
        }
        if (t4 == 0) {
            {
                float o0 = p00 + b3_0, o1 = p10 + b3_1;
                float pm = tanhf(o0 * isc0) * sc0;
                float pl = tanhf(o1 * isc1) * sc1;
                float zl = z_logstd[b0i * L_ + l], zmn = z_mean[b0i * L_ + l];
                float dmu = zmn - pm;
                float kld = pl - zl + (__expf(2.0f * zl) + dmu * dmu) * 0.5f * __expf(-2.0f * pl) - 0.5f;
                atomicAdd(out + b0i, kld * 0.125f);
            }
            {
                float o0 = p01 + b3_0, o1 = p11 + b3_1;
                float pm = tanhf(o0 * isc0) * sc0;
                float pl = tanhf(o1 * isc1) * sc1;
                float zl = z_logstd[b1i * L_ + l], zmn = z_mean[b1i * L_ + l];
                float dmu = zmn - pm;
                float kld = pl - zl + (__expf(2.0f * zl) + dmu * dmu) * 0.5f * __expf(-2.0f * pl) - 0.5f;
                atomicAdd(out + b1i, kld * 0.125f);
            }
        }
    }
}

extern "C" void kernel_launch(void* const* d_in, const int* in_sizes, int n_in,
                              void* d_out, int out_size) {
    const float* z_sample      = (const float*)d_in[0];
    const int*   target        = (const int*)  d_in[1];
    const float* z_mean        = (const float*)d_in[2];
    const float* z_logstd      = (const float*)d_in[3];
    const float* z_shared      = (const float*)d_in[4];
    const float* u_gumbel      = (const float*)d_in[5];
    const float* u_adj         = (const float*)d_in[6];
    const float* target_params = (const float*)d_in[7];
    const float* enco_theta    = (const float*)d_in[8];
    const float* enco_gamma    = (const float*)d_in[9];
    const float* W1            = (const float*)d_in[10];
    const float* b1            = (const float*)d_in[11];
    const float* gn1_w         = (const float*)d_in[12];
    const float* gn1_b         = (const float*)d_in[13];
    const float* W2            = (const float*)d_in[14];
    const float* b2            = (const float*)d_in[15];
    const float* gn2_w         = (const float*)d_in[16];
    const float* gn2_b         = (const float*)d_in[17];
    const float* W3            = (const float*)d_in[18];
    const float* b3            = (const float*)d_in[19];
    const float* tanh_scale    = (const float*)d_in[20];
    float* out = (float*)d_out;

    prep_kernel<<<B_, 256>>>(target_params, u_gumbel, enco_theta, enco_gamma, u_adj, out);

    cudaFuncSetAttribute(main_kernel, cudaFuncAttributeMaxDynamicSharedMemorySize, SMEM_BYTES);
    main_kernel<<<GRID_MAIN, 256, SMEM_BYTES>>>(
        z_sample, target, z_mean, z_logstd, z_shared,
        W1, b1, gn1_w, gn1_b, W2, b2, gn2_w, gn2_b, W3, b3, tanh_scale, out);
}